// round 12
// baseline (speedup 1.0000x reference)
#include <cuda_runtime.h>
#include <cstdint>

// ---------------------------------------------------------------------------
// MultiHeadedEMA == causal + anti-causal first-order EMA per (head, channel).
//   fwd: u[t] = q*u[t-1] + x[t] ;  rev: u[t] = q*u[t+1] + x[t]
//   out[b,l,d] = sum_h wf[h,d]*uf + wr[h,d]*ur,  w = expansion*reduction*a
// Round-12: kernel B parallelizes fwd/rev across warp halves (256 threads:
// warps 0-3 fwd, warps 4-7 rev -> serial path per thread halves, regs drop,
// occupancy rises). Combine pass adds the two smem partial buffers and
// streams out. Kernel A (aggregates) unchanged - already near DRAM floor.
// ---------------------------------------------------------------------------

constexpr int kB = 2;
constexpr int kL = 2048;
constexpr int kD = 1024;
constexpr int kH = 8;

constexpr int kChunk   = 16;
constexpr int kNChunk  = kL / kChunk;             // 128
constexpr int kCols    = 256;                     // d-columns per block
constexpr int kThreadsA = 128;
constexpr int kThreadsB = 256;                    // 128 fwd + 128 rev lanes
constexpr int kDTiles  = kD / kCols;              // 4
constexpr int kBlocks  = kB * kNChunk * kDTiles;  // 1024

// Per-chunk end states (fwd / rev), L2-resident scratch (16 MB).
__device__ __align__(16) float g_sf[kB][kNChunk][kH][kD];
__device__ __align__(16) float g_sr[kB][kNChunk][kH][kD];

using u64 = unsigned long long;

__device__ __forceinline__ u64 pack2(float lo, float hi) {
    u64 r;
    asm("mov.b64 %0, {%1, %2};"
        : "=l"(r) : "r"(__float_as_uint(lo)), "r"(__float_as_uint(hi)));
    return r;
}
__device__ __forceinline__ u64 fma2(u64 a, u64 b, u64 c) {
    u64 r;
    asm("fma.rn.f32x2 %0, %1, %2, %3;" : "=l"(r) : "l"(a), "l"(b), "l"(c));
    return r;
}
__device__ __forceinline__ u64 add2(u64 a, u64 b) {
    u64 r;
    asm("add.rn.f32x2 %0, %1, %2;" : "=l"(r) : "l"(a), "l"(b));
    return r;
}
__device__ __forceinline__ void store_cs(u64* p, u64 v) {
    float2 f;
    f.x = __uint_as_float((unsigned)(v & 0xffffffffull));
    f.y = __uint_as_float((unsigned)(v >> 32));
    __stcs(reinterpret_cast<float2*>(p), f);
}

// fp32 sigmoid; use sigp(-v) for the (1 - sigmoid(v)) term (no cancellation).
__device__ __forceinline__ float sigp(float v) { return 1.0f / (1.0f + expf(-v)); }

// ---------------------------------------------------------------------------
// Kernel A: per-chunk local scans (zero-init), publish fwd/rev end states.
// x chunk cached in registers; x read from DRAM exactly once.
// ---------------------------------------------------------------------------
__global__ void __launch_bounds__(kThreadsA)
ema_agg(const float* __restrict__ x,
        const float* __restrict__ al,  const float* __restrict__ da,
        const float* __restrict__ ral, const float* __restrict__ rda)
{
    __shared__ float s_q[2][kH];

    const int tid = threadIdx.x;
    if (tid < 2 * kH) {
        const int dir = tid >= kH;
        const int h   = tid & (kH - 1);
        const float av = dir ? ral[h] : al[h];
        const float dv = dir ? rda[h] : da[h];
        s_q[dir][h] = sigp(-av) * sigp(dv);
    }

    const int blk = blockIdx.x;
    const int dt = blk & (kDTiles - 1);
    const int c  = (blk >> 2) & (kNChunk - 1);
    const int b  = blk >> 9;

    const u64* xs = reinterpret_cast<const u64*>(
        x + ((size_t)b * kL + (size_t)c * kChunk) * kD + dt * kCols) + tid;
    const int d = dt * kCols + 2 * tid;

    u64 xv[kChunk];
#pragma unroll
    for (int i = 0; i < kChunk; ++i) xv[i] = xs[i * (kD / 2)];

    __syncthreads();

    u64 q2[kH], s[kH];
#pragma unroll
    for (int h = 0; h < kH; ++h) {
        float q = s_q[0][h];
        q2[h] = pack2(q, q);
        s[h] = 0ull;
    }
#pragma unroll
    for (int i = 0; i < kChunk; ++i)
#pragma unroll
        for (int h = 0; h < kH; ++h) s[h] = fma2(q2[h], s[h], xv[i]);
#pragma unroll
    for (int h = 0; h < kH; ++h)
        *reinterpret_cast<u64*>(&g_sf[b][c][h][d]) = s[h];

#pragma unroll
    for (int h = 0; h < kH; ++h) {
        float q = s_q[1][h];
        q2[h] = pack2(q, q);
        s[h] = 0ull;
    }
#pragma unroll
    for (int i = kChunk - 1; i >= 0; --i)
#pragma unroll
        for (int h = 0; h < kH; ++h) s[h] = fma2(q2[h], s[h], xv[i]);
#pragma unroll
    for (int h = 0; h < kH; ++h)
        *reinterpret_cast<u64*>(&g_sr[b][c][h][d]) = s[h];
}

// ---------------------------------------------------------------------------
// Kernel B: warps 0-3 = forward direction, warps 4-7 = reverse direction.
// Each half: windowed lookback over aggregates + seeded rescan into its own
// smem partial buffer. Then one sync + coalesced combine to out.
// ---------------------------------------------------------------------------
__global__ void __launch_bounds__(kThreadsB)
ema_out(const float* __restrict__ x,
        const float* __restrict__ ex,  const float* __restrict__ re,
        const float* __restrict__ al,  const float* __restrict__ da,
        const float* __restrict__ ral, const float* __restrict__ rda,
        float* __restrict__ out)
{
    __shared__ u64 accF[kChunk * 128];               // 16 KB fwd partials
    __shared__ u64 accR[kChunk * 128];               // 16 KB rev partials
    __shared__ float s_q[2][kH], s_a[2][kH], s_qc[2][kH];
    __shared__ int s_W[2];

    const int tid = threadIdx.x;
    if (tid < 2 * kH) {
        const int dr = tid >= kH;
        const int h  = tid & (kH - 1);
        const float av = dr ? ral[h] : al[h];
        const float dv = dr ? rda[h] : da[h];
        s_a[dr][h] = sigp(av);
        float q = sigp(-av) * sigp(dv);
        s_q[dr][h] = q;
        float qc = q;
#pragma unroll
        for (int k = 0; k < 4; ++k) qc *= qc;        // q^16
        s_qc[dr][h] = qc;
    }
    __syncthreads();
    if (tid < 2) {
        float m = 0.0f;
#pragma unroll
        for (int h = 0; h < kH; ++h) m = fmaxf(m, s_qc[tid][h]);
        // W = ceil(ln(1e-8)/ln(qcmax)), clamped to full history.
        int W = kNChunk;
        if (m <= 0.0f) W = 0;
        else {
            float lq = logf(m);
            if (lq < -1e-20f) {
                float w = ceilf(-18.4207f / lq);
                W = (w >= (float)kNChunk) ? kNChunk : (int)w;
            }
        }
        s_W[tid] = W;
    }

    const int blk = blockIdx.x;
    const int dt = blk & (kDTiles - 1);
    const int c  = (blk >> 2) & (kNChunk - 1);
    const int b  = blk >> 9;

    const int dir = tid >> 7;                        // 0 = fwd, 1 = rev
    const int wg  = tid & 127;                       // lane within half

    const u64* xs = reinterpret_cast<const u64*>(
        x + ((size_t)b * kL + (size_t)c * kChunk) * kD + dt * kCols) + wg;
    const int d = dt * kCols + 2 * wg;
    const int dh = d >> 1;

    const u64* bs = reinterpret_cast<const u64*>(dir ? (const float*)g_sr
                                                     : (const float*)g_sf) +
                    (size_t)b * kNChunk * kH * (kD / 2) + dh;

    __syncthreads();

    // ---- lookback prefix for this direction ----
    u64 u[kH];
    float wk[kH];
#pragma unroll
    for (int h = 0; h < kH; ++h) { u[h] = 0ull; wk[h] = 1.0f; }

    const int W = dir ? min(s_W[1], kNChunk - 1 - c) : min(s_W[0], c);
    for (int k = 0; k < W; ++k) {
        const int row = dir ? (c + 1 + k) : (c - 1 - k);
        const u64* rp = bs + (size_t)row * kH * (kD / 2);
#pragma unroll
        for (int h = 0; h < kH; ++h) {
            u64 sv = rp[h * (kD / 2)];
            u[h] = fma2(pack2(wk[h], wk[h]), sv, u[h]);
            wk[h] *= s_qc[dir][h];
        }
    }

    // ---- seeded rescan for this direction ----
    u64 q2[kH], w[kH];
#pragma unroll
    for (int h = 0; h < kH; ++h) {
        float q = s_q[dir][h], a = s_a[dir][h];
        q2[h] = pack2(q, q);
        const int hr = dir ? (kH + h) : h;
        float e0 = ex[hr * kD + d], e1 = ex[hr * kD + d + 1];
        float r0 = re[hr * kD + d], r1 = re[hr * kD + d + 1];
        w[h] = pack2(e0 * r0 * a, e1 * r1 * a);
    }

    if (dir == 0) {
#pragma unroll
        for (int i = 0; i < kChunk; ++i) {
            u64 xv = xs[i * (kD / 2)];
            u64 fs = 0ull;
#pragma unroll
            for (int h = 0; h < kH; ++h) {
                u[h] = fma2(q2[h], u[h], xv);
                fs   = fma2(w[h], u[h], fs);
            }
            accF[i * 128 + wg] = fs;
        }
    } else {
#pragma unroll
        for (int i = kChunk - 1; i >= 0; --i) {
            u64 xv = xs[i * (kD / 2)];
            u64 rs = 0ull;
#pragma unroll
            for (int h = 0; h < kH; ++h) {
                u[h] = fma2(q2[h], u[h], xv);
                rs   = fma2(w[h], u[h], rs);
            }
            accR[i * 128 + wg] = rs;
        }
    }

    __syncthreads();

    // ---- combine: out = accF + accR, coalesced, written once ----
    u64* ob = reinterpret_cast<u64*>(
        out + ((size_t)b * kL + (size_t)c * kChunk) * kD + dt * kCols);
#pragma unroll
    for (int k = 0; k < (kChunk * 128) / kThreadsB; ++k) {
        const int j   = tid + k * kThreadsB;
        const int i   = j >> 7;
        const int col = j & 127;
        store_cs(ob + (size_t)i * (kD / 2) + col, add2(accF[j], accR[j]));
    }
}

// ---------------------------------------------------------------------------
extern "C" void kernel_launch(void* const* d_in, const int* in_sizes, int n_in,
                              void* d_out, int out_size)
{
    const float* x   = (const float*)d_in[0];
    const float* ex  = (const float*)d_in[1];
    const float* re  = (const float*)d_in[2];
    const float* al  = (const float*)d_in[3];
    const float* da  = (const float*)d_in[4];
    const float* ral = (const float*)d_in[5];
    const float* rda = (const float*)d_in[6];
    float* out = (float*)d_out;

    ema_agg<<<kBlocks, kThreadsA>>>(x, al, da, ral, rda);
    ema_out<<<kBlocks, kThreadsB>>>(x, ex, re, al, da, ral, rda, out);
}